// round 1
// baseline (speedup 1.0000x reference)
#include <cuda_runtime.h>
#include <cstdint>

// Problem constants
// C_IN=8, H=W=32, C_OUT=32, K=4, S=2, P=1, HO=WO=16
// IN_FEAT = 8192, OUT_FEAT = 8192
// Output layout (float32, concatenated tuple):
//   [0 , 16384)                : out_bounds [2,32,16,16]
//   [16384 , 16384+8192*8192)  : W_mat [8192, 8192]
//   [16384+8192*8192 , +8192)  : bias_backsub [8192]

#define OUT_FEAT 8192
#define IN_FEAT  8192

// ---------------------------------------------------------------------------
// Kernel 1: interval-conv bounds + bias_backsub.
// One warp per output element o = co*256 + ho*16 + wo. Each lane handles 4 of
// the 128 (ci,kh,kw) terms, then warp-shuffle reduce. The back-substituted
// bound equals the forward bound exactly (same linear map), so the reference's
// where()-tighten reduces to this single value.
// ---------------------------------------------------------------------------
__global__ void bounds_kernel(const float* __restrict__ bounds,
                              const float* __restrict__ weight,
                              const float* __restrict__ bias,
                              float* __restrict__ out_bounds,
                              float* __restrict__ bias_backsub) {
    int warp = (blockIdx.x * blockDim.x + threadIdx.x) >> 5;   // 0..8191
    int lane = threadIdx.x & 31;
    if (warp >= OUT_FEAT) return;

    int co = warp >> 8;
    int ho = (warp >> 4) & 15;
    int wo = warp & 15;

    const float* l = bounds;           // [8,32,32]
    const float* u = bounds + 8192;

    float lo = 0.f, up = 0.f;
#pragma unroll
    for (int j = 0; j < 4; ++j) {
        int idx = lane * 4 + j;        // ci*16 + kh*4 + kw  (128 terms)
        int ci = idx >> 4;
        int kh = (idx >> 2) & 3;
        int kw = idx & 3;
        int h = ho * 2 - 1 + kh;       // stride 2, pad 1
        int w = wo * 2 - 1 + kw;
        if ((unsigned)h < 32u && (unsigned)w < 32u) {
            float wt = __ldg(&weight[((co * 8 + ci) * 4 + kh) * 4 + kw]);
            float wp = fmaxf(wt, 0.f);
            float wm = fminf(wt, 0.f);
            int ii = ci * 1024 + h * 32 + w;
            float lv = __ldg(&l[ii]);
            float uv = __ldg(&u[ii]);
            lo = fmaf(wp, lv, fmaf(wm, uv, lo));
            up = fmaf(wp, uv, fmaf(wm, lv, up));
        }
    }
#pragma unroll
    for (int off = 16; off; off >>= 1) {
        lo += __shfl_down_sync(0xffffffffu, lo, off);
        up += __shfl_down_sync(0xffffffffu, up, off);
    }
    if (lane == 0) {
        float b = __ldg(&bias[co]);
        out_bounds[warp]            = lo + b;   // lower  [0,co,ho,wo]
        out_bounds[OUT_FEAT + warp] = up + b;   // upper  [1,co,ho,wo]
        bias_backsub[warp]          = b;        // repeat_interleave(bias, 256)
    }
}

// ---------------------------------------------------------------------------
// Kernel 2: materialize the Toeplitz matrix W_mat[8192,8192].
// Pure streaming-store kernel: one float4 per thread (16,777,216 threads).
// W_mat[(co,ho,wo),(ci,h,w)] = weight[co,ci, h-(2ho-1), w-(2wo-1)] when both
// kernel offsets land in [0,4), else 0. ~1.5% nonzero, so weight reads are
// negligible (L1-resident 16KB); the kernel is bounded by 268 MB of STG.128.
// ---------------------------------------------------------------------------
__global__ void wmat_kernel(const float* __restrict__ weight,
                            float4* __restrict__ wmat) {
    unsigned t = blockIdx.x * blockDim.x + threadIdx.x;  // 0..16777215
    unsigned o  = t >> 11;          // row: 2048 float4 per 8192-wide row
    unsigned i  = (t & 2047u) << 2; // starting column element (multiple of 4)

    int co = o >> 8;
    int ho = (o >> 4) & 15;
    int wo = o & 15;
    int ci = i >> 10;
    int h  = (i >> 5) & 31;
    int w  = i & 31;

    int kh  = h - (ho * 2 - 1);
    int kw0 = w - (wo * 2 - 1);

    float4 v = make_float4(0.f, 0.f, 0.f, 0.f);
    if ((unsigned)kh < 4u) {
        const float* wp = weight + ((co * 8 + ci) * 4 + kh) * 4;
        if ((unsigned)(kw0    ) < 4u) v.x = __ldg(wp + kw0);
        if ((unsigned)(kw0 + 1) < 4u) v.y = __ldg(wp + kw0 + 1);
        if ((unsigned)(kw0 + 2) < 4u) v.z = __ldg(wp + kw0 + 2);
        if ((unsigned)(kw0 + 3) < 4u) v.w = __ldg(wp + kw0 + 3);
    }
    wmat[t] = v;
}

extern "C" void kernel_launch(void* const* d_in, const int* in_sizes, int n_in,
                              void* d_out, int out_size) {
    const float* bounds = (const float*)d_in[0];  // [2,8,32,32]
    const float* weight = (const float*)d_in[1];  // [32,8,4,4]
    const float* bias   = (const float*)d_in[2];  // [32]
    // d_in[3] = assignment (unused by forward)

    float* out          = (float*)d_out;
    float* out_bounds   = out;                              // 16384
    float* wmat         = out + 16384;                      // 8192*8192
    float* bias_backsub = out + 16384 + (size_t)OUT_FEAT * IN_FEAT;  // 8192

    // 8192 warps (one per output element): 1024 blocks x 256 threads
    bounds_kernel<<<1024, 256>>>(bounds, weight, bias, out_bounds, bias_backsub);

    // 16,777,216 float4 stores: 65536 blocks x 256 threads
    wmat_kernel<<<65536, 256>>>(weight, (float4*)wmat);
}

// round 2
// speedup vs baseline: 1.0487x; 1.0487x over previous
#include <cuda_runtime.h>
#include <cstdint>

// Output layout (float32):
//   [0, 16384)                 : out_bounds [2,32,16,16]
//   [16384, 16384+8192*8192)   : W_mat [8192, 8192]
//   then [+8192)               : bias_backsub [8192]
#define OUT_FEAT 8192
#define IN_FEAT  8192
#define WMAT_BLOCKS 8192   // one block per W_mat row
#define BOUNDS_BLOCKS 1024 // 8 warps/block, warp per output element

__global__ void __launch_bounds__(256) fused_kernel(
        const float* __restrict__ bounds,
        const float* __restrict__ weight,
        const float* __restrict__ bias,
        float* __restrict__ out_bounds,
        float4* __restrict__ wmat,
        float* __restrict__ bias_backsub) {
    if (blockIdx.x < WMAT_BLOCKS) {
        // ------------------------------------------------------------------
        // W_mat row o: 8192 floats = 2048 float4. 256 threads x 8 quads,
        // j-interleaved so each STG.128 is warp-contiguous (512B/instr).
        // Nonzero pattern: W_mat[o][ci,h,w] = weight[co,ci,h-hb,w-wb] when
        // both offsets fall in [0,4), hb = 2*ho-1, wb = 2*wo-1.
        // ------------------------------------------------------------------
        int o  = blockIdx.x;
        int co = o >> 8;
        int ho = (o >> 4) & 15;
        int wo = o & 15;
        int hb = ho * 2 - 1;
        int wb = wo * 2 - 1;
        const float* wco = weight + co * 128;   // [ci,kh,kw] slab, 512B
        float4* row = wmat + (size_t)o * 2048;
        int tid = threadIdx.x;

#pragma unroll
        for (int j = 0; j < 8; ++j) {
            int qi = j * 256 + tid;          // quad index in row, 0..2047
            int ci = qi >> 8;                // 256 quads per ci
            int h  = (qi >> 3) & 31;
            int w0 = (qi & 7) << 2;
            int kh  = h - hb;
            int kw0 = w0 - wb;
            float4 v = make_float4(0.f, 0.f, 0.f, 0.f);
            if ((unsigned)kh < 4u && (unsigned)(kw0 + 3) < 7u) {  // kw0 in [-3,3]
                const float* wp = wco + (ci * 4 + kh) * 4;
                if ((unsigned)(kw0    ) < 4u) v.x = __ldg(wp + kw0);
                if ((unsigned)(kw0 + 1) < 4u) v.y = __ldg(wp + kw0 + 1);
                if ((unsigned)(kw0 + 2) < 4u) v.z = __ldg(wp + kw0 + 2);
                if ((unsigned)(kw0 + 3) < 4u) v.w = __ldg(wp + kw0 + 3);
            }
            row[qi] = v;
        }
    } else {
        // ------------------------------------------------------------------
        // Bounds + bias_backsub: warp per output element. The reference's
        // back-substituted bound equals the forward interval bound (same
        // linear map), so the where()-tighten collapses to this value.
        // ------------------------------------------------------------------
        int warp = (int)(blockIdx.x - WMAT_BLOCKS) * 8 + (threadIdx.x >> 5);
        int lane = threadIdx.x & 31;
        if (warp >= OUT_FEAT) return;

        int co = warp >> 8;
        int ho = (warp >> 4) & 15;
        int wo = warp & 15;

        const float* l = bounds;           // [8,32,32]
        const float* u = bounds + 8192;

        float lo = 0.f, up = 0.f;
#pragma unroll
        for (int j = 0; j < 4; ++j) {
            int idx = lane * 4 + j;        // ci*16 + kh*4 + kw
            int ci = idx >> 4;
            int kh = (idx >> 2) & 3;
            int kw = idx & 3;
            int h = ho * 2 - 1 + kh;
            int w = wo * 2 - 1 + kw;
            if ((unsigned)h < 32u && (unsigned)w < 32u) {
                float wt = __ldg(&weight[((co * 8 + ci) * 4 + kh) * 4 + kw]);
                float wp = fmaxf(wt, 0.f);
                float wm = fminf(wt, 0.f);
                int ii = ci * 1024 + h * 32 + w;
                float lv = __ldg(&l[ii]);
                float uv = __ldg(&u[ii]);
                lo = fmaf(wp, lv, fmaf(wm, uv, lo));
                up = fmaf(wp, uv, fmaf(wm, lv, up));
            }
        }
#pragma unroll
        for (int off = 16; off; off >>= 1) {
            lo += __shfl_down_sync(0xffffffffu, lo, off);
            up += __shfl_down_sync(0xffffffffu, up, off);
        }
        if (lane == 0) {
            float b = __ldg(&bias[co]);
            out_bounds[warp]            = lo + b;
            out_bounds[OUT_FEAT + warp] = up + b;
            bias_backsub[warp]          = b;
        }
    }
}

extern "C" void kernel_launch(void* const* d_in, const int* in_sizes, int n_in,
                              void* d_out, int out_size) {
    const float* bounds = (const float*)d_in[0];  // [2,8,32,32]
    const float* weight = (const float*)d_in[1];  // [32,8,4,4]
    const float* bias   = (const float*)d_in[2];  // [32]
    // d_in[3] = assignment (unused)

    float* out          = (float*)d_out;
    float* out_bounds   = out;
    float* wmat         = out + 16384;
    float* bias_backsub = out + 16384 + (size_t)OUT_FEAT * IN_FEAT;

    fused_kernel<<<WMAT_BLOCKS + BOUNDS_BLOCKS, 256>>>(
        bounds, weight, bias, out_bounds, (float4*)wmat, bias_backsub);
}